// round 11
// baseline (speedup 1.0000x reference)
#include <cuda_runtime.h>
#include <math.h>
#include <stdint.h>

#define S_   128
#define B_   32
#define E2_  1024
#define DH_  512
#define AH_  32
#define EMB_ 256
#define V_   32000
#define MAXLEN_ 48
#define XDIM_ (E2_ + EMB_)          // 1280
#define TILE_V 128
#define NBLK_B (V_ / TILE_V)        // 250

// ---------------- scratch (static device globals; no allocation) ----------------
__device__ float g_encp[S_ * B_ * AH_];   // enc @ W1_e.T + b1   [s][b][j]
__device__ float g_hA[B_ * DH_];
__device__ float g_hB[B_ * DH_];
__device__ float g_hT[DH_ * B_];          // h_new transposed [d][b]
__device__ float g_x[B_ * XDIM_];         // [context | emb]
__device__ float g_cval[NBLK_B * B_];     // per-tile argmax candidates
__device__ int   g_cidx[NBLK_B * B_];

// ---------------- init h = 0 ----------------
__global__ void k_zero() {
    int i = blockIdx.x * blockDim.x + threadIdx.x;
    if (i < B_ * DH_) g_hA[i] = 0.0f;
}

// ---------------- one-time: enc_proj[s][b][j] = enc[s,b,:] . W1[j, 512:1536] + b1[j] ----------------
__global__ void k_encproj(const float* __restrict__ enc,
                          const float* __restrict__ W1,
                          const float* __restrict__ b1) {
    int s = blockIdx.x;
    int t = threadIdx.x;           // 256
    int j = t >> 3, l = t & 7;     // 32 j-octets, 8-way k-split
    const float* w = W1 + j * (DH_ + E2_) + DH_;
    const float* es = enc + s * B_ * E2_;
    float acc[B_];
#pragma unroll
    for (int b = 0; b < B_; b++) acc[b] = 0.0f;
    for (int k = l; k < E2_; k += 8) {
        float wv = w[k];
#pragma unroll
        for (int b = 0; b < B_; b++) acc[b] += wv * es[b * E2_ + k];
    }
#pragma unroll
    for (int b = 0; b < B_; b++) {
        float v = acc[b];
        v += __shfl_down_sync(0xffffffffu, v, 4);
        v += __shfl_down_sync(0xffffffffu, v, 2);
        v += __shfl_down_sync(0xffffffffu, v, 1);
        if (l == 0) g_encp[s * B_ * AH_ + b * AH_ + j] = v + b1[j];
    }
}

// ---------------- per step: argmax-finish + embed + attention + context ----------------
// grid = B*4 blocks (b, e-quarter), 256 threads
__global__ void k_attn(int t, int parity,
                       const float* __restrict__ enc,
                       const float* __restrict__ W1,
                       const float* __restrict__ W2,
                       const float* __restrict__ b2,
                       const float* __restrict__ emb,
                       const int* __restrict__ sosp, int sosc) {
    int b  = blockIdx.x >> 2;
    int eq = blockIdx.x & 3;
    int tid = threadIdx.x;

    __shared__ float hs[DH_];
    __shared__ float hp[AH_];
    __shared__ float w2s[AH_];
    __shared__ float sc[S_];
    __shared__ float red[2];
    __shared__ int   sid;
    __shared__ float rv2[256];
    __shared__ int   ri2[256];

    const float* hprev = parity ? g_hB : g_hA;

    // phase 0 (eq==0 only): finish previous step's argmax, gather embedding
    if (eq == 0) {
        if (t == 0) {
            if (tid == 0) sid = sosp ? sosp[0] : sosc;
        } else {
            float bv = -3.4e38f; int bi = 0;
            if (tid < NBLK_B) { bv = g_cval[tid * B_ + b]; bi = g_cidx[tid * B_ + b]; }
            rv2[tid] = bv; ri2[tid] = bi;
            __syncthreads();
            if (tid == 0) {
                float best = rv2[0]; int besti = ri2[0];
                for (int i = 1; i < NBLK_B; i++)
                    if (rv2[i] > best) { best = rv2[i]; besti = ri2[i]; }
                sid = besti;
            }
        }
        __syncthreads();
        g_x[b * XDIM_ + E2_ + tid] = emb[(size_t)sid * EMB_ + tid];  // 256 threads == EMB
    }

    // phase 1: load h, compute hproj[j] = h . W1[j, 0:512]
    for (int i = tid; i < DH_; i += 256) hs[i] = hprev[b * DH_ + i];
    if (tid < AH_) w2s[tid] = W2[tid];
    __syncthreads();
    {
        int j = tid >> 3, l = tid & 7;
        const float* w = W1 + j * (DH_ + E2_);
        float p = 0.0f;
        for (int k = l; k < DH_; k += 8) p += hs[k] * w[k];
        p += __shfl_down_sync(0xffffffffu, p, 4);
        p += __shfl_down_sync(0xffffffffu, p, 2);
        p += __shfl_down_sync(0xffffffffu, p, 1);
        if (l == 0) hp[j] = p;
    }
    __syncthreads();

    // phase 2: scores + softmax over S
    if (tid < S_) {
        const float* ep = g_encp + tid * B_ * AH_ + b * AH_;
        float v = b2[0];
#pragma unroll
        for (int j = 0; j < AH_; j++) v += fmaxf(ep[j] + hp[j], 0.0f) * w2s[j];
        sc[tid] = v;
    }
    __syncthreads();
    if (tid < 32) {
        float m = fmaxf(fmaxf(sc[tid], sc[tid + 32]), fmaxf(sc[tid + 64], sc[tid + 96]));
#pragma unroll
        for (int o = 16; o; o >>= 1) m = fmaxf(m, __shfl_xor_sync(0xffffffffu, m, o));
        if (tid == 0) red[0] = m;
    }
    __syncthreads();
    if (tid < S_) sc[tid] = expf(sc[tid] - red[0]);
    __syncthreads();
    if (tid < 32) {
        float sm = sc[tid] + sc[tid + 32] + sc[tid + 64] + sc[tid + 96];
#pragma unroll
        for (int o = 16; o; o >>= 1) sm += __shfl_xor_sync(0xffffffffu, sm, o);
        if (tid == 0) red[1] = sm;
    }
    __syncthreads();

    // phase 3: context slice (256 e per block)
    {
        int e = eq * 256 + tid;
        float inv = 1.0f / red[1];
        const float* ebase = enc + b * E2_ + e;
        float acc = 0.0f;
#pragma unroll 8
        for (int s0 = 0; s0 < S_; s0++) acc += sc[s0] * ebase[s0 * B_ * E2_];
        g_x[b * XDIM_ + e] = acc * inv;
    }
}

// ---------------- per step: GRU cell ----------------
// grid = B*64 blocks, 256 threads; warp computes one (b, d)
__global__ void k_gru(int parity,
                      const float* __restrict__ W_ih, const float* __restrict__ b_ih,
                      const float* __restrict__ W_hh, const float* __restrict__ b_hh) {
    int b  = blockIdx.x >> 6;
    int dg = blockIdx.x & 63;
    int tid = threadIdx.x;
    int w = tid >> 5, l = tid & 31;

    __shared__ float xs[XDIM_];
    __shared__ float hs[DH_];

    const float* hprev = parity ? g_hB : g_hA;
    float* hnext = parity ? g_hA : g_hB;

    for (int i = tid; i < XDIM_; i += 256) xs[i] = g_x[b * XDIM_ + i];
    for (int i = tid; i < DH_;  i += 256) hs[i] = hprev[b * DH_ + i];
    __syncthreads();

    int d = dg * 8 + w;
    const float* wr = W_ih + (size_t)d * XDIM_;
    const float* wz = wr + (size_t)DH_ * XDIM_;
    const float* wn = wz + (size_t)DH_ * XDIM_;
    float pir = 0.f, piz = 0.f, pin = 0.f;
#pragma unroll 4
    for (int k = l; k < XDIM_; k += 32) {
        float xv = xs[k];
        pir += xv * wr[k]; piz += xv * wz[k]; pin += xv * wn[k];
    }
    const float* vr = W_hh + (size_t)d * DH_;
    const float* vz = vr + (size_t)DH_ * DH_;
    const float* vn = vz + (size_t)DH_ * DH_;
    float phr = 0.f, phz = 0.f, phn = 0.f;
#pragma unroll 4
    for (int k = l; k < DH_; k += 32) {
        float hv = hs[k];
        phr += hv * vr[k]; phz += hv * vz[k]; phn += hv * vn[k];
    }
#pragma unroll
    for (int o = 16; o; o >>= 1) {
        pir += __shfl_xor_sync(0xffffffffu, pir, o);
        piz += __shfl_xor_sync(0xffffffffu, piz, o);
        pin += __shfl_xor_sync(0xffffffffu, pin, o);
        phr += __shfl_xor_sync(0xffffffffu, phr, o);
        phz += __shfl_xor_sync(0xffffffffu, phz, o);
        phn += __shfl_xor_sync(0xffffffffu, phn, o);
    }
    if (l == 0) {
        float r = 1.0f / (1.0f + expf(-(pir + b_ih[d]        + phr + b_hh[d])));
        float z = 1.0f / (1.0f + expf(-(piz + b_ih[DH_ + d]  + phz + b_hh[DH_ + d])));
        float n = tanhf(pin + b_ih[2 * DH_ + d] + r * (phn + b_hh[2 * DH_ + d]));
        float hn = (1.0f - z) * n + z * hs[d];
        hnext[b * DH_ + d] = hn;
        g_hT[d * B_ + b] = hn;
    }
}

// ---------------- per step: logits GEMM (fp32 via f32x2) + tile argmax ----------------
// grid = 250 blocks, 256 threads; tile 128v x 32b, thread = 2v x 8b (f32x2 over b-pairs)
__global__ void __launch_bounds__(256, 2)
k_logits(const float* __restrict__ Wo, const float* __restrict__ bo,
         float* __restrict__ out) {
    __shared__ float hs[128 * B_];          // 16 KB: k-chunk of hT [k_local][b]
    __shared__ float ls[TILE_V * 33];       // 16.5 KB: logits tile, padded

    int tid = threadIdx.x;
    int v0 = blockIdx.x * TILE_V;
    int vl = (tid >> 2) * 2;
    int bb = (tid & 3) * 8;

    const float* wrow0 = Wo + (size_t)(v0 + vl) * DH_;
    const float* wrow1 = wrow0 + DH_;

    unsigned long long a0[4] = {0ull, 0ull, 0ull, 0ull};
    unsigned long long a1[4] = {0ull, 0ull, 0ull, 0ull};

    for (int kc = 0; kc < DH_; kc += 128) {
        // stage hT chunk into smem (coalesced float4)
        const float4* src = reinterpret_cast<const float4*>(g_hT + kc * B_);
        float4* dst = reinterpret_cast<float4*>(hs);
#pragma unroll
        for (int i = 0; i < 4; i++) dst[tid + 256 * i] = src[tid + 256 * i];
        __syncthreads();

        for (int kl = 0; kl < 128; kl += 4) {
            float4 w0 = *reinterpret_cast<const float4*>(wrow0 + kc + kl);
            float4 w1 = *reinterpret_cast<const float4*>(wrow1 + kc + kl);
            const float* w0p = reinterpret_cast<const float*>(&w0);
            const float* w1p = reinterpret_cast<const float*>(&w1);
#pragma unroll
            for (int kk = 0; kk < 4; kk++) {
                unsigned long long w0d, w1d;
                asm("mov.b64 %0, {%1,%1};" : "=l"(w0d) : "f"(w0p[kk]));
                asm("mov.b64 %0, {%1,%1};" : "=l"(w1d) : "f"(w1p[kk]));
                const unsigned long long* hrow =
                    reinterpret_cast<const unsigned long long*>(&hs[(kl + kk) * B_ + bb]);
#pragma unroll
                for (int j = 0; j < 4; j++) {
                    unsigned long long hv = hrow[j];
                    asm("fma.rn.f32x2 %0, %1, %2, %0;" : "+l"(a0[j]) : "l"(w0d), "l"(hv));
                    asm("fma.rn.f32x2 %0, %1, %2, %0;" : "+l"(a1[j]) : "l"(w1d), "l"(hv));
                }
            }
        }
        __syncthreads();
    }

    // epilogue: unpack + bias -> smem tile
    float bo0 = bo[v0 + vl], bo1 = bo[v0 + vl + 1];
#pragma unroll
    for (int j = 0; j < 4; j++) {
        float x0, x1, y0, y1;
        asm("mov.b64 {%0,%1}, %2;" : "=f"(x0), "=f"(x1) : "l"(a0[j]));
        asm("mov.b64 {%0,%1}, %2;" : "=f"(y0), "=f"(y1) : "l"(a1[j]));
        ls[vl * 33 + bb + 2 * j]           = x0 + bo0;
        ls[vl * 33 + bb + 2 * j + 1]       = x1 + bo0;
        ls[(vl + 1) * 33 + bb + 2 * j]     = y0 + bo1;
        ls[(vl + 1) * 33 + bb + 2 * j + 1] = y1 + bo1;
    }
    __syncthreads();

    // coalesced store: warp w covers batches w*4..w*4+3, lane strides v
    {
        int w = tid >> 5, l = tid & 31;
#pragma unroll
        for (int r = 0; r < 4; r++) {
            int b = w * 4 + r;
            float4 vv;
            vv.x = ls[(l * 4 + 0) * 33 + b];
            vv.y = ls[(l * 4 + 1) * 33 + b];
            vv.z = ls[(l * 4 + 2) * 33 + b];
            vv.w = ls[(l * 4 + 3) * 33 + b];
            *reinterpret_cast<float4*>(out + (size_t)b * V_ + v0 + l * 4) = vv;
        }
    }

    // per-(tile, b) argmax candidate (first-max tie-break: ascending scan, strict >)
    {
        int b = tid & 31, g = tid >> 5;
        float best = -3.4e38f; int besti = v0;
#pragma unroll
        for (int i = 0; i < 16; i++) {
            int vv = g * 16 + i;
            float val = ls[vv * 33 + b];
            if (val > best) { best = val; besti = v0 + vv; }
        }
        float* rv = hs;                       // reuse staging smem
        int*   ri = reinterpret_cast<int*>(hs + 256);
        rv[g * 32 + b] = best;
        ri[g * 32 + b] = besti;
        __syncthreads();
        if (tid < 32) {
            float bv = rv[tid]; int bi = ri[tid];
#pragma unroll
            for (int g2 = 1; g2 < 8; g2++) {
                float v2 = rv[g2 * 32 + tid];
                if (v2 > bv) { bv = v2; bi = ri[g2 * 32 + tid]; }
            }
            g_cval[blockIdx.x * B_ + tid] = bv;
            g_cidx[blockIdx.x * B_ + tid] = bi;
        }
    }
}

// ---------------- host ----------------
extern "C" void kernel_launch(void* const* d_in, const int* in_sizes, int n_in,
                              void* d_out, int out_size) {
    // metadata order: enc, [max_length, sos_token,] emb, W1, b1, W2, b2,
    //                 W_ih, b_ih, W_hh, b_hh, Wo, bo
    int base = n_in - 11;   // index of emb (3 if scalars present, 1 otherwise)
    const float* enc  = (const float*)d_in[0];
    const int*   sosp = (n_in >= 14) ? (const int*)d_in[2] : nullptr;
    const float* emb  = (const float*)d_in[base + 0];
    const float* W1   = (const float*)d_in[base + 1];
    const float* b1   = (const float*)d_in[base + 2];
    const float* W2   = (const float*)d_in[base + 3];
    const float* b2   = (const float*)d_in[base + 4];
    const float* W_ih = (const float*)d_in[base + 5];
    const float* b_ih = (const float*)d_in[base + 6];
    const float* W_hh = (const float*)d_in[base + 7];
    const float* b_hh = (const float*)d_in[base + 8];
    const float* Wo   = (const float*)d_in[base + 9];
    const float* bo   = (const float*)d_in[base + 10];
    float* out = (float*)d_out;

    k_zero<<<64, 256>>>();
    k_encproj<<<S_, 256>>>(enc, W1, b1);

    for (int t = 0; t < MAXLEN_; t++) {
        int parity = t & 1;
        k_attn<<<B_ * 4, 256>>>(t, parity, enc, W1, W2, b2, emb, sosp, 1);
        k_gru<<<B_ * 64, 256>>>(parity, W_ih, b_ih, W_hh, b_hh);
        k_logits<<<NBLK_B, 256>>>(Wo, bo, out + (size_t)t * B_ * V_);
    }
}

// round 12
// speedup vs baseline: 1.0087x; 1.0087x over previous
#include <cuda_runtime.h>
#include <math.h>
#include <stdint.h>

#define S_   128
#define B_   32
#define E2_  1024
#define DH_  512
#define AH_  32
#define EMB_ 256
#define V_   32000
#define MAXLEN_ 48
#define XDIM_ (E2_ + EMB_)          // 1280
#define TILE_V 128
#define NBLK_B (V_ / TILE_V)        // 250

// ---------------- scratch (static device globals; no allocation) ----------------
__device__ float g_encp[S_ * B_ * AH_];   // enc @ W1_e.T + b1   [s][b][j]
__device__ float g_hA[B_ * DH_];
__device__ float g_hB[B_ * DH_];
__device__ float g_hT[DH_ * B_];          // h_new transposed [d][b]
__device__ float g_x[B_ * XDIM_];         // [context | emb]
__device__ float g_cval[NBLK_B * B_];     // per-tile argmax candidates
__device__ int   g_cidx[NBLK_B * B_];

// ---------------- init h = 0 ----------------
__global__ void k_zero() {
    int i = blockIdx.x * blockDim.x + threadIdx.x;
    if (i < B_ * DH_) g_hA[i] = 0.0f;
}

// ---------------- one-time: enc_proj[s][b][j] = enc[s,b,:] . W1[j, 512:1536] + b1[j] ----------------
__global__ void k_encproj(const float* __restrict__ enc,
                          const float* __restrict__ W1,
                          const float* __restrict__ b1) {
    int s = blockIdx.x;
    int t = threadIdx.x;           // 256
    int j = t >> 3, l = t & 7;     // 32 j-octets, 8-way k-split
    const float* w = W1 + j * (DH_ + E2_) + DH_;
    const float* es = enc + s * B_ * E2_;
    float acc[B_];
#pragma unroll
    for (int b = 0; b < B_; b++) acc[b] = 0.0f;
    for (int k = l; k < E2_; k += 8) {
        float wv = w[k];
#pragma unroll
        for (int b = 0; b < B_; b++) acc[b] += wv * es[b * E2_ + k];
    }
#pragma unroll
    for (int b = 0; b < B_; b++) {
        float v = acc[b];
        v += __shfl_down_sync(0xffffffffu, v, 4);
        v += __shfl_down_sync(0xffffffffu, v, 2);
        v += __shfl_down_sync(0xffffffffu, v, 1);
        if (l == 0) g_encp[s * B_ * AH_ + b * AH_ + j] = v + b1[j];
    }
}

// ---------------- per step: argmax-finish + embed + attention + context ----------------
// grid = B*4 blocks (b, e-quarter), 256 threads
__global__ void k_attn(int t, int parity,
                       const float* __restrict__ enc,
                       const float* __restrict__ W1,
                       const float* __restrict__ W2,
                       const float* __restrict__ b2,
                       const float* __restrict__ emb,
                       const int* __restrict__ sosp, int sosc) {
    int b  = blockIdx.x >> 2;
    int eq = blockIdx.x & 3;
    int tid = threadIdx.x;

    __shared__ float hs[DH_];
    __shared__ float hp[AH_];
    __shared__ float w2s[AH_];
    __shared__ float sc[S_];
    __shared__ float red[2];
    __shared__ int   sid;
    __shared__ float rv2[256];
    __shared__ int   ri2[256];

    const float* hprev = parity ? g_hB : g_hA;

    // phase 0 (eq==0 only): finish previous step's argmax, gather embedding
    if (eq == 0) {
        if (t == 0) {
            if (tid == 0) sid = sosp ? sosp[0] : sosc;
        } else {
            float bv = -3.4e38f; int bi = 0;
            if (tid < NBLK_B) { bv = g_cval[tid * B_ + b]; bi = g_cidx[tid * B_ + b]; }
            rv2[tid] = bv; ri2[tid] = bi;
            __syncthreads();
            if (tid == 0) {
                float best = rv2[0]; int besti = ri2[0];
                for (int i = 1; i < NBLK_B; i++)
                    if (rv2[i] > best) { best = rv2[i]; besti = ri2[i]; }
                sid = besti;
            }
        }
        __syncthreads();
        g_x[b * XDIM_ + E2_ + tid] = emb[(size_t)sid * EMB_ + tid];  // 256 threads == EMB
    }

    // phase 1: load h, compute hproj[j] = h . W1[j, 0:512]
    for (int i = tid; i < DH_; i += 256) hs[i] = hprev[b * DH_ + i];
    if (tid < AH_) w2s[tid] = W2[tid];
    __syncthreads();
    {
        int j = tid >> 3, l = tid & 7;
        const float* w = W1 + j * (DH_ + E2_);
        float p = 0.0f;
        for (int k = l; k < DH_; k += 8) p += hs[k] * w[k];
        p += __shfl_down_sync(0xffffffffu, p, 4);
        p += __shfl_down_sync(0xffffffffu, p, 2);
        p += __shfl_down_sync(0xffffffffu, p, 1);
        if (l == 0) hp[j] = p;
    }
    __syncthreads();

    // phase 2: scores + softmax over S
    if (tid < S_) {
        const float* ep = g_encp + tid * B_ * AH_ + b * AH_;
        float v = b2[0];
#pragma unroll
        for (int j = 0; j < AH_; j++) v += fmaxf(ep[j] + hp[j], 0.0f) * w2s[j];
        sc[tid] = v;
    }
    __syncthreads();
    if (tid < 32) {
        float m = fmaxf(fmaxf(sc[tid], sc[tid + 32]), fmaxf(sc[tid + 64], sc[tid + 96]));
#pragma unroll
        for (int o = 16; o; o >>= 1) m = fmaxf(m, __shfl_xor_sync(0xffffffffu, m, o));
        if (tid == 0) red[0] = m;
    }
    __syncthreads();
    if (tid < S_) sc[tid] = expf(sc[tid] - red[0]);
    __syncthreads();
    if (tid < 32) {
        float sm = sc[tid] + sc[tid + 32] + sc[tid + 64] + sc[tid + 96];
#pragma unroll
        for (int o = 16; o; o >>= 1) sm += __shfl_xor_sync(0xffffffffu, sm, o);
        if (tid == 0) red[1] = sm;
    }
    __syncthreads();

    // phase 3: context slice (256 e per block)
    {
        int e = eq * 256 + tid;
        float inv = 1.0f / red[1];
        const float* ebase = enc + b * E2_ + e;
        float acc = 0.0f;
#pragma unroll 8
        for (int s0 = 0; s0 < S_; s0++) acc += sc[s0] * ebase[s0 * B_ * E2_];
        g_x[b * XDIM_ + e] = acc * inv;
    }
}

// ---------------- per step: GRU cell ----------------
// grid = B*64 blocks, 256 threads; warp computes one (b, d)
__global__ void k_gru(int parity,
                      const float* __restrict__ W_ih, const float* __restrict__ b_ih,
                      const float* __restrict__ W_hh, const float* __restrict__ b_hh) {
    int b  = blockIdx.x >> 6;
    int dg = blockIdx.x & 63;
    int tid = threadIdx.x;
    int w = tid >> 5, l = tid & 31;

    __shared__ float xs[XDIM_];
    __shared__ float hs[DH_];

    const float* hprev = parity ? g_hB : g_hA;
    float* hnext = parity ? g_hA : g_hB;

    for (int i = tid; i < XDIM_; i += 256) xs[i] = g_x[b * XDIM_ + i];
    for (int i = tid; i < DH_;  i += 256) hs[i] = hprev[b * DH_ + i];
    __syncthreads();

    int d = dg * 8 + w;
    const float* wr = W_ih + (size_t)d * XDIM_;
    const float* wz = wr + (size_t)DH_ * XDIM_;
    const float* wn = wz + (size_t)DH_ * XDIM_;
    float pir = 0.f, piz = 0.f, pin = 0.f;
#pragma unroll 4
    for (int k = l; k < XDIM_; k += 32) {
        float xv = xs[k];
        pir += xv * wr[k]; piz += xv * wz[k]; pin += xv * wn[k];
    }
    const float* vr = W_hh + (size_t)d * DH_;
    const float* vz = vr + (size_t)DH_ * DH_;
    const float* vn = vz + (size_t)DH_ * DH_;
    float phr = 0.f, phz = 0.f, phn = 0.f;
#pragma unroll 4
    for (int k = l; k < DH_; k += 32) {
        float hv = hs[k];
        phr += hv * vr[k]; phz += hv * vz[k]; phn += hv * vn[k];
    }
#pragma unroll
    for (int o = 16; o; o >>= 1) {
        pir += __shfl_xor_sync(0xffffffffu, pir, o);
        piz += __shfl_xor_sync(0xffffffffu, piz, o);
        pin += __shfl_xor_sync(0xffffffffu, pin, o);
        phr += __shfl_xor_sync(0xffffffffu, phr, o);
        phz += __shfl_xor_sync(0xffffffffu, phz, o);
        phn += __shfl_xor_sync(0xffffffffu, phn, o);
    }
    if (l == 0) {
        float r = 1.0f / (1.0f + expf(-(pir + b_ih[d]        + phr + b_hh[d])));
        float z = 1.0f / (1.0f + expf(-(piz + b_ih[DH_ + d]  + phz + b_hh[DH_ + d])));
        float n = tanhf(pin + b_ih[2 * DH_ + d] + r * (phn + b_hh[2 * DH_ + d]));
        float hn = (1.0f - z) * n + z * hs[d];
        hnext[b * DH_ + d] = hn;
        g_hT[d * B_ + b] = hn;
    }
}

// ---------------- per step: logits GEMM (fp32 via f32x2) + tile argmax ----------------
// grid = 250 blocks, 256 threads; tile 128v x 32b, thread = 2v x 8b (f32x2 over b-pairs)
__global__ void __launch_bounds__(256, 2)
k_logits(const float* __restrict__ Wo, const float* __restrict__ bo,
         float* __restrict__ out) {
    __shared__ float hs[128 * B_];          // 16 KB: k-chunk of hT [k_local][b]
    __shared__ float ls[TILE_V * 33];       // 16.5 KB: logits tile, padded

    int tid = threadIdx.x;
    int v0 = blockIdx.x * TILE_V;
    int vl = (tid >> 2) * 2;
    int bb = (tid & 3) * 8;

    const float* wrow0 = Wo + (size_t)(v0 + vl) * DH_;
    const float* wrow1 = wrow0 + DH_;

    unsigned long long a0[4] = {0ull, 0ull, 0ull, 0ull};
    unsigned long long a1[4] = {0ull, 0ull, 0ull, 0ull};

    for (int kc = 0; kc < DH_; kc += 128) {
        // stage hT chunk into smem (coalesced float4)
        const float4* src = reinterpret_cast<const float4*>(g_hT + kc * B_);
        float4* dst = reinterpret_cast<float4*>(hs);
#pragma unroll
        for (int i = 0; i < 4; i++) dst[tid + 256 * i] = src[tid + 256 * i];
        __syncthreads();

        for (int kl = 0; kl < 128; kl += 4) {
            float4 w0 = *reinterpret_cast<const float4*>(wrow0 + kc + kl);
            float4 w1 = *reinterpret_cast<const float4*>(wrow1 + kc + kl);
            const float* w0p = reinterpret_cast<const float*>(&w0);
            const float* w1p = reinterpret_cast<const float*>(&w1);
#pragma unroll
            for (int kk = 0; kk < 4; kk++) {
                unsigned long long w0d, w1d;
                asm("mov.b64 %0, {%1,%1};" : "=l"(w0d) : "f"(w0p[kk]));
                asm("mov.b64 %0, {%1,%1};" : "=l"(w1d) : "f"(w1p[kk]));
                const unsigned long long* hrow =
                    reinterpret_cast<const unsigned long long*>(&hs[(kl + kk) * B_ + bb]);
#pragma unroll
                for (int j = 0; j < 4; j++) {
                    unsigned long long hv = hrow[j];
                    asm("fma.rn.f32x2 %0, %1, %2, %0;" : "+l"(a0[j]) : "l"(w0d), "l"(hv));
                    asm("fma.rn.f32x2 %0, %1, %2, %0;" : "+l"(a1[j]) : "l"(w1d), "l"(hv));
                }
            }
        }
        __syncthreads();
    }

    // epilogue: unpack + bias -> smem tile
    float bo0 = bo[v0 + vl], bo1 = bo[v0 + vl + 1];
#pragma unroll
    for (int j = 0; j < 4; j++) {
        float x0, x1, y0, y1;
        asm("mov.b64 {%0,%1}, %2;" : "=f"(x0), "=f"(x1) : "l"(a0[j]));
        asm("mov.b64 {%0,%1}, %2;" : "=f"(y0), "=f"(y1) : "l"(a1[j]));
        ls[vl * 33 + bb + 2 * j]           = x0 + bo0;
        ls[vl * 33 + bb + 2 * j + 1]       = x1 + bo0;
        ls[(vl + 1) * 33 + bb + 2 * j]     = y0 + bo1;
        ls[(vl + 1) * 33 + bb + 2 * j + 1] = y1 + bo1;
    }
    __syncthreads();

    // coalesced store: warp w covers batches w*4..w*4+3, lane strides v
    {
        int w = tid >> 5, l = tid & 31;
#pragma unroll
        for (int r = 0; r < 4; r++) {
            int b = w * 4 + r;
            float4 vv;
            vv.x = ls[(l * 4 + 0) * 33 + b];
            vv.y = ls[(l * 4 + 1) * 33 + b];
            vv.z = ls[(l * 4 + 2) * 33 + b];
            vv.w = ls[(l * 4 + 3) * 33 + b];
            *reinterpret_cast<float4*>(out + (size_t)b * V_ + v0 + l * 4) = vv;
        }
    }

    // per-(tile, b) argmax candidate (first-max tie-break: ascending scan, strict >)
    {
        int b = tid & 31, g = tid >> 5;
        float best = -3.4e38f; int besti = v0;
#pragma unroll
        for (int i = 0; i < 16; i++) {
            int vv = g * 16 + i;
            float val = ls[vv * 33 + b];
            if (val > best) { best = val; besti = v0 + vv; }
        }
        float* rv = hs;                       // reuse staging smem
        int*   ri = reinterpret_cast<int*>(hs + 256);
        rv[g * 32 + b] = best;
        ri[g * 32 + b] = besti;
        __syncthreads();
        if (tid < 32) {
            float bv = rv[tid]; int bi = ri[tid];
#pragma unroll
            for (int g2 = 1; g2 < 8; g2++) {
                float v2 = rv[g2 * 32 + tid];
                if (v2 > bv) { bv = v2; bi = ri[g2 * 32 + tid]; }
            }
            g_cval[blockIdx.x * B_ + tid] = bv;
            g_cidx[blockIdx.x * B_ + tid] = bi;
        }
    }
}

// ---------------- host ----------------
extern "C" void kernel_launch(void* const* d_in, const int* in_sizes, int n_in,
                              void* d_out, int out_size) {
    // metadata order: enc, [max_length, sos_token,] emb, W1, b1, W2, b2,
    //                 W_ih, b_ih, W_hh, b_hh, Wo, bo
    int base = n_in - 11;   // index of emb (3 if scalars present, 1 otherwise)
    const float* enc  = (const float*)d_in[0];
    const int*   sosp = (n_in >= 14) ? (const int*)d_in[2] : nullptr;
    const float* emb  = (const float*)d_in[base + 0];
    const float* W1   = (const float*)d_in[base + 1];
    const float* b1   = (const float*)d_in[base + 2];
    const float* W2   = (const float*)d_in[base + 3];
    const float* b2   = (const float*)d_in[base + 4];
    const float* W_ih = (const float*)d_in[base + 5];
    const float* b_ih = (const float*)d_in[base + 6];
    const float* W_hh = (const float*)d_in[base + 7];
    const float* b_hh = (const float*)d_in[base + 8];
    const float* Wo   = (const float*)d_in[base + 9];
    const float* bo   = (const float*)d_in[base + 10];
    float* out = (float*)d_out;

    k_zero<<<64, 256>>>();
    k_encproj<<<S_, 256>>>(enc, W1, b1);

    for (int t = 0; t < MAXLEN_; t++) {
        int parity = t & 1;
        k_attn<<<B_ * 4, 256>>>(t, parity, enc, W1, W2, b2, emb, sosp, 1);
        k_gru<<<B_ * 64, 256>>>(parity, W_ih, b_ih, W_hh, b_hh);
        k_logits<<<NBLK_B, 256>>>(Wo, bo, out + (size_t)t * B_ * V_);
    }
}

// round 13
// speedup vs baseline: 1.0092x; 1.0005x over previous
#include <cuda_runtime.h>
#include <math.h>
#include <stdint.h>

#define S_   128
#define B_   32
#define E2_  1024
#define DH_  512
#define AH_  32
#define EMB_ 256
#define V_   32000
#define MAXLEN_ 48
#define XDIM_ (E2_ + EMB_)          // 1280
#define TILE_V 128
#define NBLK_B (V_ / TILE_V)        // 250

// ---------------- scratch (static device globals; no allocation) ----------------
__device__ float g_encp[S_ * B_ * AH_];   // enc @ W1_e.T + b1   [s][b][j]
__device__ float g_hA[B_ * DH_];
__device__ float g_hB[B_ * DH_];
__device__ float g_hT[DH_ * B_];          // h_new transposed [d][b]
__device__ float g_x[B_ * XDIM_];         // [context | emb]
__device__ float g_cval[NBLK_B * B_];     // per-tile argmax candidates
__device__ int   g_cidx[NBLK_B * B_];

// ---------------- init h = 0 ----------------
__global__ void k_zero() {
    int i = blockIdx.x * blockDim.x + threadIdx.x;
    if (i < B_ * DH_) g_hA[i] = 0.0f;
}

// ---------------- one-time: enc_proj[s][b][j] = enc[s,b,:] . W1[j, 512:1536] + b1[j] ----------------
__global__ void k_encproj(const float* __restrict__ enc,
                          const float* __restrict__ W1,
                          const float* __restrict__ b1) {
    int s = blockIdx.x;
    int t = threadIdx.x;           // 256
    int j = t >> 3, l = t & 7;     // 32 j-octets, 8-way k-split
    const float* w = W1 + j * (DH_ + E2_) + DH_;
    const float* es = enc + s * B_ * E2_;
    float acc[B_];
#pragma unroll
    for (int b = 0; b < B_; b++) acc[b] = 0.0f;
    for (int k = l; k < E2_; k += 8) {
        float wv = w[k];
#pragma unroll
        for (int b = 0; b < B_; b++) acc[b] += wv * es[b * E2_ + k];
    }
#pragma unroll
    for (int b = 0; b < B_; b++) {
        float v = acc[b];
        v += __shfl_down_sync(0xffffffffu, v, 4);
        v += __shfl_down_sync(0xffffffffu, v, 2);
        v += __shfl_down_sync(0xffffffffu, v, 1);
        if (l == 0) g_encp[s * B_ * AH_ + b * AH_ + j] = v + b1[j];
    }
}

// ---------------- per step: argmax-finish + embed + attention + context ----------------
// grid = B*4 blocks (b, e-quarter), 256 threads
__global__ void k_attn(int t, int parity,
                       const float* __restrict__ enc,
                       const float* __restrict__ W1,
                       const float* __restrict__ W2,
                       const float* __restrict__ b2,
                       const float* __restrict__ emb,
                       const int* __restrict__ sosp, int sosc) {
    int b  = blockIdx.x >> 2;
    int eq = blockIdx.x & 3;
    int tid = threadIdx.x;

    __shared__ float hs[DH_];
    __shared__ float hp[AH_];
    __shared__ float w2s[AH_];
    __shared__ float sc[S_];
    __shared__ float red[2];
    __shared__ int   sid;
    __shared__ float rv2[256];
    __shared__ int   ri2[256];

    const float* hprev = parity ? g_hB : g_hA;

    // phase 0 (eq==0 only): finish previous step's argmax, gather embedding
    if (eq == 0) {
        if (t == 0) {
            if (tid == 0) sid = sosp ? sosp[0] : sosc;
        } else {
            float bv = -3.4e38f; int bi = 0;
            if (tid < NBLK_B) { bv = g_cval[tid * B_ + b]; bi = g_cidx[tid * B_ + b]; }
            rv2[tid] = bv; ri2[tid] = bi;
            __syncthreads();
            if (tid == 0) {
                float best = rv2[0]; int besti = ri2[0];
                for (int i = 1; i < NBLK_B; i++)
                    if (rv2[i] > best) { best = rv2[i]; besti = ri2[i]; }
                sid = besti;
            }
        }
        __syncthreads();
        g_x[b * XDIM_ + E2_ + tid] = emb[(size_t)sid * EMB_ + tid];  // 256 threads == EMB
    }

    // phase 1: load h, compute hproj[j] = h . W1[j, 0:512]
    for (int i = tid; i < DH_; i += 256) hs[i] = hprev[b * DH_ + i];
    if (tid < AH_) w2s[tid] = W2[tid];
    __syncthreads();
    {
        int j = tid >> 3, l = tid & 7;
        const float* w = W1 + j * (DH_ + E2_);
        float p = 0.0f;
        for (int k = l; k < DH_; k += 8) p += hs[k] * w[k];
        p += __shfl_down_sync(0xffffffffu, p, 4);
        p += __shfl_down_sync(0xffffffffu, p, 2);
        p += __shfl_down_sync(0xffffffffu, p, 1);
        if (l == 0) hp[j] = p;
    }
    __syncthreads();

    // phase 2: scores + softmax over S
    if (tid < S_) {
        const float* ep = g_encp + tid * B_ * AH_ + b * AH_;
        float v = b2[0];
#pragma unroll
        for (int j = 0; j < AH_; j++) v += fmaxf(ep[j] + hp[j], 0.0f) * w2s[j];
        sc[tid] = v;
    }
    __syncthreads();
    if (tid < 32) {
        float m = fmaxf(fmaxf(sc[tid], sc[tid + 32]), fmaxf(sc[tid + 64], sc[tid + 96]));
#pragma unroll
        for (int o = 16; o; o >>= 1) m = fmaxf(m, __shfl_xor_sync(0xffffffffu, m, o));
        if (tid == 0) red[0] = m;
    }
    __syncthreads();
    if (tid < S_) sc[tid] = expf(sc[tid] - red[0]);
    __syncthreads();
    if (tid < 32) {
        float sm = sc[tid] + sc[tid + 32] + sc[tid + 64] + sc[tid + 96];
#pragma unroll
        for (int o = 16; o; o >>= 1) sm += __shfl_xor_sync(0xffffffffu, sm, o);
        if (tid == 0) red[1] = sm;
    }
    __syncthreads();

    // phase 3: context slice (256 e per block)
    {
        int e = eq * 256 + tid;
        float inv = 1.0f / red[1];
        const float* ebase = enc + b * E2_ + e;
        float acc = 0.0f;
#pragma unroll 8
        for (int s0 = 0; s0 < S_; s0++) acc += sc[s0] * ebase[s0 * B_ * E2_];
        g_x[b * XDIM_ + e] = acc * inv;
    }
}

// ---------------- per step: GRU cell ----------------
// grid = B*64 blocks, 256 threads; warp computes one (b, d)
__global__ void k_gru(int parity,
                      const float* __restrict__ W_ih, const float* __restrict__ b_ih,
                      const float* __restrict__ W_hh, const float* __restrict__ b_hh) {
    int b  = blockIdx.x >> 6;
    int dg = blockIdx.x & 63;
    int tid = threadIdx.x;
    int w = tid >> 5, l = tid & 31;

    __shared__ float xs[XDIM_];
    __shared__ float hs[DH_];

    const float* hprev = parity ? g_hB : g_hA;
    float* hnext = parity ? g_hA : g_hB;

    for (int i = tid; i < XDIM_; i += 256) xs[i] = g_x[b * XDIM_ + i];
    for (int i = tid; i < DH_;  i += 256) hs[i] = hprev[b * DH_ + i];
    __syncthreads();

    int d = dg * 8 + w;
    const float* wr = W_ih + (size_t)d * XDIM_;
    const float* wz = wr + (size_t)DH_ * XDIM_;
    const float* wn = wz + (size_t)DH_ * XDIM_;
    float pir = 0.f, piz = 0.f, pin = 0.f;
#pragma unroll 4
    for (int k = l; k < XDIM_; k += 32) {
        float xv = xs[k];
        pir += xv * wr[k]; piz += xv * wz[k]; pin += xv * wn[k];
    }
    const float* vr = W_hh + (size_t)d * DH_;
    const float* vz = vr + (size_t)DH_ * DH_;
    const float* vn = vz + (size_t)DH_ * DH_;
    float phr = 0.f, phz = 0.f, phn = 0.f;
#pragma unroll 4
    for (int k = l; k < DH_; k += 32) {
        float hv = hs[k];
        phr += hv * vr[k]; phz += hv * vz[k]; phn += hv * vn[k];
    }
#pragma unroll
    for (int o = 16; o; o >>= 1) {
        pir += __shfl_xor_sync(0xffffffffu, pir, o);
        piz += __shfl_xor_sync(0xffffffffu, piz, o);
        pin += __shfl_xor_sync(0xffffffffu, pin, o);
        phr += __shfl_xor_sync(0xffffffffu, phr, o);
        phz += __shfl_xor_sync(0xffffffffu, phz, o);
        phn += __shfl_xor_sync(0xffffffffu, phn, o);
    }
    if (l == 0) {
        float r = 1.0f / (1.0f + expf(-(pir + b_ih[d]        + phr + b_hh[d])));
        float z = 1.0f / (1.0f + expf(-(piz + b_ih[DH_ + d]  + phz + b_hh[DH_ + d])));
        float n = tanhf(pin + b_ih[2 * DH_ + d] + r * (phn + b_hh[2 * DH_ + d]));
        float hn = (1.0f - z) * n + z * hs[d];
        hnext[b * DH_ + d] = hn;
        g_hT[d * B_ + b] = hn;
    }
}

// ---------------- per step: logits GEMM (fp32 via f32x2) + tile argmax ----------------
// grid = 250 blocks, 256 threads; tile 128v x 32b, thread = 2v x 8b (f32x2 over b-pairs)
__global__ void __launch_bounds__(256, 2)
k_logits(const float* __restrict__ Wo, const float* __restrict__ bo,
         float* __restrict__ out) {
    __shared__ float hs[128 * B_];          // 16 KB: k-chunk of hT [k_local][b]
    __shared__ float ls[TILE_V * 33];       // 16.5 KB: logits tile, padded

    int tid = threadIdx.x;
    int v0 = blockIdx.x * TILE_V;
    int vl = (tid >> 2) * 2;
    int bb = (tid & 3) * 8;

    const float* wrow0 = Wo + (size_t)(v0 + vl) * DH_;
    const float* wrow1 = wrow0 + DH_;

    unsigned long long a0[4] = {0ull, 0ull, 0ull, 0ull};
    unsigned long long a1[4] = {0ull, 0ull, 0ull, 0ull};

    for (int kc = 0; kc < DH_; kc += 128) {
        // stage hT chunk into smem (coalesced float4)
        const float4* src = reinterpret_cast<const float4*>(g_hT + kc * B_);
        float4* dst = reinterpret_cast<float4*>(hs);
#pragma unroll
        for (int i = 0; i < 4; i++) dst[tid + 256 * i] = src[tid + 256 * i];
        __syncthreads();

        for (int kl = 0; kl < 128; kl += 4) {
            float4 w0 = *reinterpret_cast<const float4*>(wrow0 + kc + kl);
            float4 w1 = *reinterpret_cast<const float4*>(wrow1 + kc + kl);
            const float* w0p = reinterpret_cast<const float*>(&w0);
            const float* w1p = reinterpret_cast<const float*>(&w1);
#pragma unroll
            for (int kk = 0; kk < 4; kk++) {
                unsigned long long w0d, w1d;
                asm("mov.b64 %0, {%1,%1};" : "=l"(w0d) : "f"(w0p[kk]));
                asm("mov.b64 %0, {%1,%1};" : "=l"(w1d) : "f"(w1p[kk]));
                const unsigned long long* hrow =
                    reinterpret_cast<const unsigned long long*>(&hs[(kl + kk) * B_ + bb]);
#pragma unroll
                for (int j = 0; j < 4; j++) {
                    unsigned long long hv = hrow[j];
                    asm("fma.rn.f32x2 %0, %1, %2, %0;" : "+l"(a0[j]) : "l"(w0d), "l"(hv));
                    asm("fma.rn.f32x2 %0, %1, %2, %0;" : "+l"(a1[j]) : "l"(w1d), "l"(hv));
                }
            }
        }
        __syncthreads();
    }

    // epilogue: unpack + bias -> smem tile
    float bo0 = bo[v0 + vl], bo1 = bo[v0 + vl + 1];
#pragma unroll
    for (int j = 0; j < 4; j++) {
        float x0, x1, y0, y1;
        asm("mov.b64 {%0,%1}, %2;" : "=f"(x0), "=f"(x1) : "l"(a0[j]));
        asm("mov.b64 {%0,%1}, %2;" : "=f"(y0), "=f"(y1) : "l"(a1[j]));
        ls[vl * 33 + bb + 2 * j]           = x0 + bo0;
        ls[vl * 33 + bb + 2 * j + 1]       = x1 + bo0;
        ls[(vl + 1) * 33 + bb + 2 * j]     = y0 + bo1;
        ls[(vl + 1) * 33 + bb + 2 * j + 1] = y1 + bo1;
    }
    __syncthreads();

    // coalesced store: warp w covers batches w*4..w*4+3, lane strides v
    {
        int w = tid >> 5, l = tid & 31;
#pragma unroll
        for (int r = 0; r < 4; r++) {
            int b = w * 4 + r;
            float4 vv;
            vv.x = ls[(l * 4 + 0) * 33 + b];
            vv.y = ls[(l * 4 + 1) * 33 + b];
            vv.z = ls[(l * 4 + 2) * 33 + b];
            vv.w = ls[(l * 4 + 3) * 33 + b];
            *reinterpret_cast<float4*>(out + (size_t)b * V_ + v0 + l * 4) = vv;
        }
    }

    // per-(tile, b) argmax candidate (first-max tie-break: ascending scan, strict >)
    {
        int b = tid & 31, g = tid >> 5;
        float best = -3.4e38f; int besti = v0;
#pragma unroll
        for (int i = 0; i < 16; i++) {
            int vv = g * 16 + i;
            float val = ls[vv * 33 + b];
            if (val > best) { best = val; besti = v0 + vv; }
        }
        float* rv = hs;                       // reuse staging smem
        int*   ri = reinterpret_cast<int*>(hs + 256);
        rv[g * 32 + b] = best;
        ri[g * 32 + b] = besti;
        __syncthreads();
        if (tid < 32) {
            float bv = rv[tid]; int bi = ri[tid];
#pragma unroll
            for (int g2 = 1; g2 < 8; g2++) {
                float v2 = rv[g2 * 32 + tid];
                if (v2 > bv) { bv = v2; bi = ri[g2 * 32 + tid]; }
            }
            g_cval[blockIdx.x * B_ + tid] = bv;
            g_cidx[blockIdx.x * B_ + tid] = bi;
        }
    }
}

// ---------------- host ----------------
extern "C" void kernel_launch(void* const* d_in, const int* in_sizes, int n_in,
                              void* d_out, int out_size) {
    // metadata order: enc, [max_length, sos_token,] emb, W1, b1, W2, b2,
    //                 W_ih, b_ih, W_hh, b_hh, Wo, bo
    int base = n_in - 11;   // index of emb (3 if scalars present, 1 otherwise)
    const float* enc  = (const float*)d_in[0];
    const int*   sosp = (n_in >= 14) ? (const int*)d_in[2] : nullptr;
    const float* emb  = (const float*)d_in[base + 0];
    const float* W1   = (const float*)d_in[base + 1];
    const float* b1   = (const float*)d_in[base + 2];
    const float* W2   = (const float*)d_in[base + 3];
    const float* b2   = (const float*)d_in[base + 4];
    const float* W_ih = (const float*)d_in[base + 5];
    const float* b_ih = (const float*)d_in[base + 6];
    const float* W_hh = (const float*)d_in[base + 7];
    const float* b_hh = (const float*)d_in[base + 8];
    const float* Wo   = (const float*)d_in[base + 9];
    const float* bo   = (const float*)d_in[base + 10];
    float* out = (float*)d_out;

    k_zero<<<64, 256>>>();
    k_encproj<<<S_, 256>>>(enc, W1, b1);

    for (int t = 0; t < MAXLEN_; t++) {
        int parity = t & 1;
        k_attn<<<B_ * 4, 256>>>(t, parity, enc, W1, W2, b2, emb, sosp, 1);
        k_gru<<<B_ * 64, 256>>>(parity, W_ih, b_ih, W_hh, b_hh);
        k_logits<<<NBLK_B, 256>>>(Wo, bo, out + (size_t)t * B_ * V_);
    }
}